// round 9
// baseline (speedup 1.0000x reference)
#include <cuda_runtime.h>

#define RC        8.0f
#define PI_F      3.14159265358979323846f
#define MAX_ATOMS 27000
#define FPSCALE   32768.0f
#define INV_FPSCALE (1.0f / 32768.0f)

// fixed-point packed atoms: x:21b (+/-32), y:21b (+/-32), z:20b (+/-16), type:2b
__device__ uint2 g_q[MAX_ATOMS + 1];

static __device__ __forceinline__ float fsqrt_approx(float x) {
    float y; asm("sqrt.approx.f32 %0, %1;" : "=f"(y) : "f"(x)); return y;
}
static __device__ __forceinline__ float fcos_approx(float x) {
    float y; asm("cos.approx.f32 %0, %1;" : "=f"(y) : "f"(x)); return y;
}

__global__ void pack_kernel(const int* __restrict__ types,
                            const float* __restrict__ pos, int n)
{
    int i = blockIdx.x * blockDim.x + threadIdx.x;
    if (i < n) {
        const int xq = __float2int_rn(pos[i * 3 + 0] * FPSCALE);
        const int yq = __float2int_rn(pos[i * 3 + 1] * FPSCALE);
        const int zq = __float2int_rn(pos[i * 3 + 2] * FPSCALE);
        const unsigned t = (unsigned)types[i];
        uint2 w;
        w.x = ((unsigned)xq & 0x1FFFFFu) | ((unsigned)yq << 21);
        w.y = (((unsigned)yq >> 11) & 0x3FFu)
            | (((unsigned)zq & 0xFFFFFu) << 10)
            | (t << 30);
        g_q[i] = w;
    }
    if (i == n) {
        // dummy: x = +31 units -> r > RC for any real atom -> h = 0
        uint2 w;
        w.x = (unsigned)(31 * 32768) & 0x1FFFFFu;
        w.y = 0u;
        g_q[n] = w;
    }
}

static __device__ __forceinline__ void unpack_q(uint2 w, int& x, int& y, int& z, int& t) {
    x = ((int)(w.x << 11)) >> 11;
    const unsigned y21 = (w.x >> 21) | ((w.y & 0x3FFu) << 11);
    y = ((int)(y21 << 11)) >> 11;
    z = ((int)(w.y << 2)) >> 12;
    t = (int)(w.y >> 30);
}

// One 1024-thread CTA per SM (32 warps). Packed atom table (160 KB) lives in
// dynamic smem -> per-edge random gather is LDS.64 (~10x cheaper than the
// L1tex 32-line LDG replay chain). 8 lanes/atom, 4 atoms/warp, 128 atoms/iter.
__global__ __launch_bounds__(1024, 1) void radial_desc_kernel(
    const int*   __restrict__ nbr,
    const float* __restrict__ offs,
    const float* __restrict__ ctab,
    float*       __restrict__ out,
    int n_atoms, int n_cta)
{
    extern __shared__ char smem[];
    uint2* tab = reinterpret_cast<uint2*>(smem);
    const int n1 = n_atoms + 1;
    float* c_sh = reinterpret_cast<float*>(smem + (((size_t)n1 * 8 + 15) & ~(size_t)15));

    // cooperative table + coeff load (L2-broadcast across CTAs)
    for (int i = threadIdx.x; i < n1; i += 1024) tab[i] = g_q[i];
    for (int i = threadIdx.x; i < 1024; i += 1024) c_sh[i] = ctab[i];
    __syncthreads();

    const int c     = blockIdx.x;
    const int start = (int)(((long long)c * n_atoms) / n_cta);
    const int end   = (int)(((long long)(c + 1) * n_atoms) / n_cta);
    const int count = end - start;

    const int lane = threadIdx.x & 31;
    const int warp = threadIdx.x >> 5;
    const int s    = lane & 7;    // lane within 8-lane group
    const int g    = lane >> 3;   // atom slot within warp

    const bool hi4 = (s & 4) != 0;
    const bool hi2 = (s & 2) != 0;
    const bool hi1 = (s & 1) != 0;

    for (int base = warp * 4; base < count; base += 128) {
        const int gi   = base + g;
        const bool ok  = gi < count;
        const int atom = start + (ok ? gi : (count - 1));

        int xa, ya, za, ti;
        unpack_q(tab[atom], xa, ya, za, ti);

        float G[4][8];
        #pragma unroll
        for (int t = 0; t < 4; t++)
            #pragma unroll
            for (int k = 0; k < 8; k++)
                G[t][k] = 0.0f;

        const int4*   nb4 = reinterpret_cast<const int4*>(nbr)    + (long)atom * 16 + s * 2;
        const float4* ob4 = reinterpret_cast<const float4*>(offs) + (long)atom * 48 + s * 6;

        #pragma unroll
        for (int half = 0; half < 2; half++) {
            const int4 nv = __ldcs(nb4 + half);

            int ia[4];
            ia[0] = (nv.x < 0) ? n_atoms : nv.x;
            ia[1] = (nv.y < 0) ? n_atoms : nv.y;
            ia[2] = (nv.z < 0) ? n_atoms : nv.z;
            ia[3] = (nv.w < 0) ? n_atoms : nv.w;

            uint2 W[4];
            #pragma unroll
            for (int e = 0; e < 4; e++)
                W[e] = tab[ia[e]];                 // LDS.64 gathers

            const float4 f0 = __ldcs(ob4 + half * 3 + 0);
            const float4 f1 = __ldcs(ob4 + half * 3 + 1);
            const float4 f2 = __ldcs(ob4 + half * 3 + 2);
            const float ox[4] = { f0.x, f0.w, f1.z, f2.y };
            const float oy[4] = { f0.y, f1.x, f1.w, f2.z };
            const float oz[4] = { f0.z, f1.y, f2.x, f2.w };

            #pragma unroll
            for (int e = 0; e < 4; e++) {
                int xj, yj, zj, tj;
                unpack_q(W[e], xj, yj, zj, tj);

                const float dx = fmaf((float)(xj - xa), INV_FPSCALE, ox[e]);
                const float dy = fmaf((float)(yj - ya), INV_FPSCALE, oy[e]);
                const float dz = fmaf((float)(zj - za), INV_FPSCALE, oz[e]);

                const float r2 = dx * dx + dy * dy + dz * dz;
                const float r  = fsqrt_approx(r2);

                float h = 0.25f * fcos_approx(r * (PI_F / RC)) + 0.25f;
                h = (r < RC) ? h : 0.0f;

                const float u  = r * (1.0f / RC) - 1.0f;
                const float x  = 2.0f * u * u - 1.0f;
                const float tw = x + x;

                float T[8];
                T[1] = x;
                T[2] = tw * x - 1.0f;
                #pragma unroll
                for (int k = 3; k < 8; k++) T[k] = tw * T[k - 1] - T[k - 2];

                #pragma unroll
                for (int t = 0; t < 4; t++) {
                    const float wh = (tj == t) ? h : 0.0f;
                    G[t][0] += wh;                    // T0 == 1
                    #pragma unroll
                    for (int k = 1; k < 8; k++) G[t][k] += wh * T[k];
                }
            }
        }

        // ---- halving-butterfly reduction of 32 values over the 8-lane group ----
        float* v = &G[0][0];
        float v1[16];
        #pragma unroll
        for (int i = 0; i < 16; i++) {
            const float send = hi4 ? v[i] : v[i + 16];
            const float recv = __shfl_xor_sync(0xffffffffu, send, 4);
            v1[i] = (hi4 ? v[i + 16] : v[i]) + recv;
        }
        float v2[8];
        #pragma unroll
        for (int i = 0; i < 8; i++) {
            const float send = hi2 ? v1[i] : v1[i + 8];
            const float recv = __shfl_xor_sync(0xffffffffu, send, 2);
            v2[i] = (hi2 ? v1[i + 8] : v1[i]) + recv;
        }
        float v3[4];
        #pragma unroll
        for (int i = 0; i < 4; i++) {
            const float send = hi1 ? v2[i] : v2[i + 4];
            const float recv = __shfl_xor_sync(0xffffffffu, send, 1);
            v3[i] = (hi1 ? v2[i + 4] : v2[i]) + recv;
        }
        // lane s holds totals for t = ((s&4)>>1)|((s&2)>>1), k = (s&1)*4 + k'
        const int tl = ((s & 4) >> 1) | ((s & 2) >> 1);

        // F[t][k] = G[t][k] + G[t][0]  (folds the (T_k + 1) term)
        const float g0 = __shfl_sync(0xffffffffu, v3[0], lane & ~1);
        const float F0 = v3[0] + g0;
        const float F1 = v3[1] + g0;
        const float F2 = v3[2] + g0;
        const float F3 = v3[3] + g0;

        const float4* c4p = reinterpret_cast<const float4*>(c_sh);
        const int cbase = ((ti * 4 + tl) * 8) * 2 + (s & 1);
        float p[8];
        #pragma unroll
        for (int d = 0; d < 8; d++) {
            const float4 cc = c4p[cbase + d * 2];
            p[d] = cc.x * F0 + cc.y * F1 + cc.z * F2 + cc.w * F3;
        }

        float q[4];
        #pragma unroll
        for (int i = 0; i < 4; i++) {
            const float send = hi4 ? p[i] : p[i + 4];
            const float recv = __shfl_xor_sync(0xffffffffu, send, 4);
            q[i] = (hi4 ? p[i + 4] : p[i]) + recv;
        }
        float rr[2];
        #pragma unroll
        for (int i = 0; i < 2; i++) {
            const float send = hi2 ? q[i] : q[i + 2];
            const float recv = __shfl_xor_sync(0xffffffffu, send, 2);
            rr[i] = (hi2 ? q[i + 2] : q[i]) + recv;
        }
        {
            const float send = hi1 ? rr[0] : rr[1];
            const float recv = __shfl_xor_sync(0xffffffffu, send, 1);
            const float o = (hi1 ? rr[1] : rr[0]) + recv;
            if (ok) out[(long)atom * 8 + s] = o;
        }
    }
}

extern "C" void kernel_launch(void* const* d_in, const int* in_sizes, int n_in,
                              void* d_out, int out_size) {
    const int*   types = (const int*)  d_in[0];
    const float* pos   = (const float*)d_in[1];
    const int*   nbr   = (const int*)  d_in[2];
    const float* offs  = (const float*)d_in[3];
    const float* ctab  = (const float*)d_in[4];
    float* out = (float*)d_out;

    int n_atoms = in_sizes[0];
    if (n_atoms > MAX_ATOMS) n_atoms = MAX_ATOMS;

    pack_kernel<<<(n_atoms + 1 + 255) / 256, 256>>>(types, pos, n_atoms);

    int n_sm = 148;
    cudaDeviceGetAttribute(&n_sm, cudaDevAttrMultiProcessorCount, 0);

    const size_t tab_bytes = (((size_t)(n_atoms + 1) * 8 + 15) & ~(size_t)15);
    const size_t sh_bytes  = tab_bytes + 1024 * sizeof(float);

    static int configured_bytes = 0;
    if ((int)sh_bytes != configured_bytes) {
        cudaFuncSetAttribute(radial_desc_kernel,
                             cudaFuncAttributeMaxDynamicSharedMemorySize,
                             (int)sh_bytes);
        configured_bytes = (int)sh_bytes;
    }

    radial_desc_kernel<<<n_sm, 1024, sh_bytes>>>(nbr, offs, ctab, out,
                                                 n_atoms, n_sm);
}